// round 1
// baseline (speedup 1.0000x reference)
#include <cuda_runtime.h>
#include <cuda_bf16.h>

// Grouped GEMM: C[e] = A[e] (M x K) @ B[e]^T (B is N x K, K-major) -> C (E x M x N)
// Rows m >= expert_num_tokens[e] are written as zeros.
// E=32, M=1024, K=512, N=512 (fp32).

#define BM 128
#define BN 128
#define BK 8
#define TM 8
#define TN 8
#define NTHREADS 256  // (BM/TM)*(BN/TN)

__global__ __launch_bounds__(NTHREADS, 2)
void grouped_gemm_f32_kernel(const float* __restrict__ A,
                             const float* __restrict__ B,
                             const int* __restrict__ expert_num_tokens,
                             float* __restrict__ C,
                             int M, int N, int K)
{
    const int e  = blockIdx.z;
    const int m0 = blockIdx.y * BM;
    const int n0 = blockIdx.x * BN;
    const int nt = expert_num_tokens[e];

    float* __restrict__ Ce = C + (size_t)e * M * N;
    const int tid = threadIdx.x;

    // ---- Fast path: tile entirely below the valid-row cutoff -> zero-fill ----
    if (m0 >= nt) {
        const float4 z = make_float4(0.f, 0.f, 0.f, 0.f);
        #pragma unroll 4
        for (int i = tid; i < BM * (BN / 4); i += NTHREADS) {
            int r = i / (BN / 4);
            int c = (i % (BN / 4)) * 4;
            *reinterpret_cast<float4*>(&Ce[(size_t)(m0 + r) * N + (n0 + c)]) = z;
        }
        return;
    }

    const float* __restrict__ Ae = A + (size_t)e * M * K;
    const float* __restrict__ Be = B + (size_t)e * N * K;

    __shared__ float As[BK][BM];   // K-major: As[k][m]
    __shared__ float Bs[BK][BN];   // K-major: Bs[k][n]

    // Global-load mapping: 256 threads, each loads one float4 of A and one of B per k-step.
    const int lrow = tid >> 1;          // 0..127 (row within tile)
    const int lcol = (tid & 1) * 4;     // 0 or 4 (k offset within BK)

    // Compute mapping: 16x16 thread grid, 8x8 microtile each.
    const int tx = tid & 15;            // n direction
    const int ty = tid >> 4;            // m direction
    const int mm = ty * TM;
    const int nn = tx * TN;

    float acc[TM][TN];
    #pragma unroll
    for (int i = 0; i < TM; i++)
        #pragma unroll
        for (int j = 0; j < TN; j++)
            acc[i][j] = 0.f;

    for (int k0 = 0; k0 < K; k0 += BK) {
        const float4 av = *reinterpret_cast<const float4*>(&Ae[(size_t)(m0 + lrow) * K + k0 + lcol]);
        const float4 bv = *reinterpret_cast<const float4*>(&Be[(size_t)(n0 + lrow) * K + k0 + lcol]);

        __syncthreads();  // protect previous iteration's smem reads
        As[lcol + 0][lrow] = av.x;
        As[lcol + 1][lrow] = av.y;
        As[lcol + 2][lrow] = av.z;
        As[lcol + 3][lrow] = av.w;
        Bs[lcol + 0][lrow] = bv.x;
        Bs[lcol + 1][lrow] = bv.y;
        Bs[lcol + 2][lrow] = bv.z;
        Bs[lcol + 3][lrow] = bv.w;
        __syncthreads();

        #pragma unroll
        for (int kk = 0; kk < BK; kk++) {
            float a[TM], b[TN];
            // vectorized smem reads (32B-aligned: mm, nn are multiples of 8)
            const float4 a0 = *reinterpret_cast<const float4*>(&As[kk][mm]);
            const float4 a1 = *reinterpret_cast<const float4*>(&As[kk][mm + 4]);
            const float4 b0 = *reinterpret_cast<const float4*>(&Bs[kk][nn]);
            const float4 b1 = *reinterpret_cast<const float4*>(&Bs[kk][nn + 4]);
            a[0] = a0.x; a[1] = a0.y; a[2] = a0.z; a[3] = a0.w;
            a[4] = a1.x; a[5] = a1.y; a[6] = a1.z; a[7] = a1.w;
            b[0] = b0.x; b[1] = b0.y; b[2] = b0.z; b[3] = b0.w;
            b[4] = b1.x; b[5] = b1.y; b[6] = b1.z; b[7] = b1.w;

            #pragma unroll
            for (int i = 0; i < TM; i++)
                #pragma unroll
                for (int j = 0; j < TN; j++)
                    acc[i][j] = fmaf(a[i], b[j], acc[i][j]);
        }
    }

    // ---- Store with per-row validity masking (zeros for invalid rows) ----
    #pragma unroll
    for (int i = 0; i < TM; i++) {
        const int m = m0 + mm + i;
        float4 v0, v1;
        if (m < nt) {
            v0 = make_float4(acc[i][0], acc[i][1], acc[i][2], acc[i][3]);
            v1 = make_float4(acc[i][4], acc[i][5], acc[i][6], acc[i][7]);
        } else {
            v0 = make_float4(0.f, 0.f, 0.f, 0.f);
            v1 = v0;
        }
        *reinterpret_cast<float4*>(&Ce[(size_t)m * N + n0 + nn])     = v0;
        *reinterpret_cast<float4*>(&Ce[(size_t)m * N + n0 + nn + 4]) = v1;
    }
}

extern "C" void kernel_launch(void* const* d_in, const int* in_sizes, int n_in,
                              void* d_out, int out_size)
{
    const float* A   = (const float*)d_in[0];          // [E, M, K]
    const float* B   = (const float*)d_in[1];          // [E, N, K]
    const int*   ent = (const int*)d_in[2];            // [E]
    float*       C   = (float*)d_out;                  // [E, M, N]

    const int K = 512;
    const int N = 512;
    const int E = in_sizes[2];
    const int M = in_sizes[0] / (E * K);

    dim3 grid(N / BN, M / BM, E);   // (4, 8, 32) — expert on z (slowest) for L2 reuse
    dim3 block(NTHREADS);
    grouped_gemm_f32_kernel<<<grid, block>>>(A, B, ent, C, M, N, K);
}

// round 3
// speedup vs baseline: 3.0131x; 3.0131x over previous
#include <cuda_runtime.h>
#include <cuda_bf16.h>
#include <cstdint>

// Grouped GEMM C[e] = A[e] @ B[e]^T via tcgen05 bf16-split (3-MMA fp32 emulation).
// E=32, M=1024, K=512, N=512 fp32. Rows m >= expert_num_tokens[e] -> 0.
//
// tcgen05 is sm_103a-specific; the build also runs a compute_103 (portable) PTX
// pass, so all tcgen05 code is guarded by __CUDA_ARCH_FEAT_SM103_ALL with an
// FFMA fallback body for the portable pass (never executed on GB300).

#define E_ 32
#define M_ 1024
#define K_ 512
#define N_ 512

#define BM 128
#define BN 128
#define BK 64            // bf16 elems per chunk = 128 bytes/row (SW128)
#define NCHUNK (K_/BK)   // 8
#define NTHR 128

#if defined(__CUDA_ARCH__) && !defined(__CUDA_ARCH_FEAT_SM103_ALL) && !defined(__CUDA_ARCH_FEAT_SM100_ALL)
#define TC_FALLBACK 1
#else
#define TC_FALLBACK 0
#endif

// ---- scratch: bf16 hi/lo split of A and B (zero-init at module load) ----
__device__ __align__(16) __nv_bfloat16 g_Ah[E_*M_*K_];
__device__ __align__(16) __nv_bfloat16 g_Al[E_*M_*K_];
__device__ __align__(16) __nv_bfloat16 g_Bh[E_*N_*K_];
__device__ __align__(16) __nv_bfloat16 g_Bl[E_*N_*K_];

// ======================= PTX helpers (arch-portable ones) =======================
__device__ __forceinline__ uint32_t smem_u32(const void* p) {
    uint32_t a;
    asm("{ .reg .u64 t; cvta.to.shared.u64 t, %1; cvt.u32.u64 %0, t; }" : "=r"(a) : "l"(p));
    return a;
}
__device__ __forceinline__ uint32_t elect_one() {
    uint32_t pred;
    asm volatile("{ .reg .pred p; elect.sync _|p, 0xFFFFFFFF; selp.b32 %0, 1, 0, p; }" : "=r"(pred));
    return pred;
}
#define MBAR_INIT(addr, cnt) \
    asm volatile("mbarrier.init.shared.b64 [%0], %1;" :: "r"(addr), "r"(cnt) : "memory")
#define MBAR_INVAL(addr) \
    asm volatile("mbarrier.inval.shared.b64 [%0];" :: "r"(addr) : "memory")

__device__ __forceinline__ void mbar_wait(uint32_t mbar, uint32_t parity) {
    uint32_t done;
    asm volatile("{ .reg .pred p; mbarrier.try_wait.parity.acquire.cta.shared::cta.b64 p, [%1], %2; selp.b32 %0,1,0,p; }"
                 : "=r"(done) : "r"(mbar), "r"(parity) : "memory");
    if (!done) {
        asm volatile("{ .reg .pred P1;\n"
                     "WL_%=: mbarrier.try_wait.parity.acquire.cta.shared::cta.b64 P1, [%0], %1, 0x989680;\n"
                     "@P1 bra.uni WD_%=;\n bra.uni WL_%=;\n WD_%=: }"
                     :: "r"(mbar), "r"(parity) : "memory");
    }
}

__device__ __forceinline__ void cp16(uint32_t s, const void* g) {
    asm volatile("cp.async.cg.shared.global [%0], [%1], 16;" :: "r"(s), "l"(g));
}
#define CP_COMMIT() asm volatile("cp.async.commit_group;" ::: "memory")
#define CP_WAIT(n)  asm volatile("cp.async.wait_group %0;" :: "n"(n) : "memory")
#define FENCE_ASYNC() asm volatile("fence.proxy.async.shared::cta;" ::: "memory")

// ======================= tcgen05 helpers (sm_103a-only pass) =======================
#if !TC_FALLBACK
#define TC_ALLOC(smem_addr, ncols) \
    asm volatile("tcgen05.alloc.cta_group::1.sync.aligned.shared::cta.b32 [%0], %1;" \
                 :: "r"(smem_addr), "r"(ncols) : "memory")
#define TC_DEALLOC(tmem, ncols) \
    asm volatile("tcgen05.dealloc.cta_group::1.sync.aligned.b32 %0, %1;" :: "r"(tmem), "r"(ncols))
#define TC_RELINQ() \
    asm volatile("tcgen05.relinquish_alloc_permit.cta_group::1.sync.aligned;")
#define TC_COMMIT(mbar) \
    asm volatile("tcgen05.commit.cta_group::1.mbarrier::arrive::one.shared::cluster.b64 [%0];" \
                 :: "r"(mbar) : "memory")
#define TC_FENCE_AFTER()  asm volatile("tcgen05.fence::after_thread_sync;" ::: "memory")
#define TC_WAIT_LD()      asm volatile("tcgen05.wait::ld.sync.aligned;" ::: "memory")

__device__ __forceinline__ void mma_f16_ss(uint32_t d, uint64_t ad, uint64_t bd,
                                           uint32_t idesc, uint32_t enable) {
    asm volatile("{ .reg .pred p; setp.ne.u32 p, %5, 0;\n"
                 "tcgen05.mma.cta_group::1.kind::f16 [%0], %1, %2, %3, {%4,%4,%4,%4}, p; }"
                 :: "r"(d), "l"(ad), "l"(bd), "r"(idesc), "r"(0u), "r"(enable) : "memory");
}

#define LDTM_X32(r, addr) \
    asm volatile("tcgen05.ld.sync.aligned.32x32b.x32.b32 " \
        "{%0,%1,%2,%3,%4,%5,%6,%7,%8,%9,%10,%11,%12,%13,%14,%15," \
        "%16,%17,%18,%19,%20,%21,%22,%23,%24,%25,%26,%27,%28,%29,%30,%31}, [%32];" \
        : "=r"((r)[0]),"=r"((r)[1]),"=r"((r)[2]),"=r"((r)[3]),"=r"((r)[4]),"=r"((r)[5]),"=r"((r)[6]),"=r"((r)[7]), \
          "=r"((r)[8]),"=r"((r)[9]),"=r"((r)[10]),"=r"((r)[11]),"=r"((r)[12]),"=r"((r)[13]),"=r"((r)[14]),"=r"((r)[15]), \
          "=r"((r)[16]),"=r"((r)[17]),"=r"((r)[18]),"=r"((r)[19]),"=r"((r)[20]),"=r"((r)[21]),"=r"((r)[22]),"=r"((r)[23]), \
          "=r"((r)[24]),"=r"((r)[25]),"=r"((r)[26]),"=r"((r)[27]),"=r"((r)[28]),"=r"((r)[29]),"=r"((r)[30]),"=r"((r)[31]) \
        : "r"(addr))
#endif // !TC_FALLBACK

// SW128 K-major descriptor (layout=2, version=1, SBO=64, LBO=1)
static constexpr uint64_t DESC_SW128 =
    (2ull << 61) | (1ull << 46) | (64ull << 32) | (1ull << 16);
__device__ __forceinline__ uint64_t sdesc(uint32_t a) {
    return DESC_SW128 | ((uint64_t)(a >> 4) & 0x3FFF);
}

// idesc: F32 accum, BF16 x BF16, M=128, N=128, K-major both
static constexpr uint32_t IDESC =
    (1u << 4) | (1u << 7) | (1u << 10) | ((BN / 8) << 17) | ((BM / 16) << 24);

// ======================= conversion prepass =======================
__global__ void __launch_bounds__(256) convertA(const float* __restrict__ A,
                                                const int* __restrict__ ent) {
    const int64_t nchunk = (int64_t)E_ * M_ * K_ / 4;
    for (int64_t i = (int64_t)blockIdx.x * blockDim.x + threadIdx.x; i < nchunk;
         i += (int64_t)gridDim.x * blockDim.x) {
        const int64_t elem = i * 4;
        const int row = (int)(elem >> 9);        // elem / K_
        const int m = row & (M_ - 1);
        const int e = row >> 10;
        if (m >= __ldg(&ent[e])) continue;       // invalid rows: scratch stays zero
        const float4 v = *reinterpret_cast<const float4*>(A + elem);
        __nv_bfloat16 h0 = __float2bfloat16(v.x), h1 = __float2bfloat16(v.y);
        __nv_bfloat16 h2 = __float2bfloat16(v.z), h3 = __float2bfloat16(v.w);
        __nv_bfloat16 l0 = __float2bfloat16(v.x - __bfloat162float(h0));
        __nv_bfloat16 l1 = __float2bfloat16(v.y - __bfloat162float(h1));
        __nv_bfloat16 l2 = __float2bfloat16(v.z - __bfloat162float(h2));
        __nv_bfloat16 l3 = __float2bfloat16(v.w - __bfloat162float(h3));
        union { __nv_bfloat16 b[4]; uint2 u; } hu, lu;
        hu.b[0] = h0; hu.b[1] = h1; hu.b[2] = h2; hu.b[3] = h3;
        lu.b[0] = l0; lu.b[1] = l1; lu.b[2] = l2; lu.b[3] = l3;
        *reinterpret_cast<uint2*>(&g_Ah[elem]) = hu.u;
        *reinterpret_cast<uint2*>(&g_Al[elem]) = lu.u;
    }
}

__global__ void __launch_bounds__(256) convertB(const float* __restrict__ B) {
    const int64_t nchunk = (int64_t)E_ * N_ * K_ / 4;
    for (int64_t i = (int64_t)blockIdx.x * blockDim.x + threadIdx.x; i < nchunk;
         i += (int64_t)gridDim.x * blockDim.x) {
        const int64_t elem = i * 4;
        const float4 v = *reinterpret_cast<const float4*>(B + elem);
        __nv_bfloat16 h0 = __float2bfloat16(v.x), h1 = __float2bfloat16(v.y);
        __nv_bfloat16 h2 = __float2bfloat16(v.z), h3 = __float2bfloat16(v.w);
        __nv_bfloat16 l0 = __float2bfloat16(v.x - __bfloat162float(h0));
        __nv_bfloat16 l1 = __float2bfloat16(v.y - __bfloat162float(h1));
        __nv_bfloat16 l2 = __float2bfloat16(v.z - __bfloat162float(h2));
        __nv_bfloat16 l3 = __float2bfloat16(v.w - __bfloat162float(h3));
        union { __nv_bfloat16 b[4]; uint2 u; } hu, lu;
        hu.b[0] = h0; hu.b[1] = h1; hu.b[2] = h2; hu.b[3] = h3;
        lu.b[0] = l0; lu.b[1] = l1; lu.b[2] = l2; lu.b[3] = l3;
        *reinterpret_cast<uint2*>(&g_Bh[elem]) = hu.u;
        *reinterpret_cast<uint2*>(&g_Bl[elem]) = lu.u;
    }
}

// ======================= tcgen05 GEMM =======================
// SMEM: [0] tmem ptr, [16],[24] mbarriers, [1024..) 2 stages x 64KB
// Stage layout: Ah(16K) Al(16K) Bh(16K) Bl(16K); rows 128B wide, SW128 swizzle.
#define SM_TMEM 0
#define SM_MBAR 16
#define SM_DATA 1024
#define STAGE_BYTES 65536
#define SMEM_TOTAL (SM_DATA + 2 * STAGE_BYTES)
#define TMEM_COLS 128

__device__ __forceinline__ void load_stage(uint32_t sbase,
                                           const __nv_bfloat16* gAh, const __nv_bfloat16* gAl,
                                           const __nv_bfloat16* gBh, const __nv_bfloat16* gBl,
                                           int tid) {
    const __nv_bfloat16* gp[4] = {gAh, gAl, gBh, gBl};
    #pragma unroll
    for (int mat = 0; mat < 4; mat++) {
        const uint32_t sb = sbase + mat * 16384;
        const char* g = (const char*)gp[mat];
        #pragma unroll
        for (int i = 0; i < 8; i++) {
            const int ch = tid + i * NTHR;      // 0..1023
            const int r = ch >> 3;
            const int j = ch & 7;
            const uint32_t off = (uint32_t)r * 128u + (uint32_t)j * 16u;
            const uint32_t sw = off ^ ((off >> 3) & 0x70);
            cp16(sb + sw, g + (size_t)r * (K_ * 2) + (size_t)j * 16);
        }
    }
}

__global__ void __launch_bounds__(NTHR, 1)
grouped_gemm_tc(const int* __restrict__ ent, float* __restrict__ C) {
    const int e  = blockIdx.z;
    const int m0 = blockIdx.y * BM;
    const int n0 = blockIdx.x * BN;
    const int nt = __ldg(&ent[e]);
    const int tid = threadIdx.x;
    const int wid = tid >> 5;
    const int lid = tid & 31;

    float* __restrict__ Ce = C + (size_t)e * M_ * N_;

    // ---- fully-invalid tile: vectorized zero-fill, no tensor work ----
    if (m0 >= nt) {
        const float4 z = make_float4(0.f, 0.f, 0.f, 0.f);
        #pragma unroll 4
        for (int i = tid; i < BM * (BN / 4); i += NTHR) {
            int r = i >> 5;           // / (BN/4)
            int c = (i & 31) << 2;
            *reinterpret_cast<float4*>(&Ce[(size_t)(m0 + r) * N_ + n0 + c]) = z;
        }
        return;
    }

#if TC_FALLBACK
    // ---- portable-PTX fallback (never executed on GB300; cubin has tcgen05 path) ----
    const __nv_bfloat16* Ah = g_Ah + ((size_t)e * M_ + m0) * K_;
    const __nv_bfloat16* Al = g_Al + ((size_t)e * M_ + m0) * K_;
    const __nv_bfloat16* Bh = g_Bh + ((size_t)e * N_ + n0) * K_;
    const __nv_bfloat16* Bl = g_Bl + ((size_t)e * N_ + n0) * K_;
    const int m = m0 + tid;            // tid 0..127 -> one M row each
    const bool valid = m < nt;
    for (int n = 0; n < BN; n++) {
        float acc = 0.f;
        if (valid) {
            for (int k = 0; k < K_; k++) {
                float a = __bfloat162float(Ah[(size_t)tid * K_ + k]) +
                          __bfloat162float(Al[(size_t)tid * K_ + k]);
                float b = __bfloat162float(Bh[(size_t)n * K_ + k]) +
                          __bfloat162float(Bl[(size_t)n * K_ + k]);
                acc = fmaf(a, b, acc);
            }
        }
        Ce[(size_t)m * N_ + n0 + n] = acc;
    }
#else
    extern __shared__ char smem[];
    const uint32_t sb = smem_u32(smem);

    if (tid == 0) {
        MBAR_INIT(sb + SM_MBAR + 0, 1);
        MBAR_INIT(sb + SM_MBAR + 8, 1);
    }
    if (wid == 0) TC_ALLOC(sb + SM_TMEM, TMEM_COLS);
    __syncthreads();
    uint32_t tmem;
    asm volatile("ld.shared.b32 %0, [%1];" : "=r"(tmem) : "r"(sb + SM_TMEM));

    const size_t aoff = ((size_t)e * M_ + m0) * K_;
    const size_t boff = ((size_t)e * N_ + n0) * K_;

    // prologue: stage 0 (chunk 0)
    load_stage(sb + SM_DATA, g_Ah + aoff, g_Al + aoff, g_Bh + boff, g_Bl + boff, tid);
    CP_COMMIT();

    int wcnt0 = 0, wcnt1 = 0;

    #pragma unroll 1
    for (int c = 0; c < NCHUNK; c++) {
        const int buf = c & 1;
        if (c + 1 < NCHUNK) {
            const int nb = (c + 1) & 1;
            if (c + 1 >= 2) {   // buffer nb was consumed by MMA chunk c-1
                if (nb == 0) { mbar_wait(sb + SM_MBAR + 0, wcnt0 & 1); wcnt0++; }
                else         { mbar_wait(sb + SM_MBAR + 8, wcnt1 & 1); wcnt1++; }
            }
            const int k1 = (c + 1) * BK;
            load_stage(sb + SM_DATA + nb * STAGE_BYTES,
                       g_Ah + aoff + k1, g_Al + aoff + k1,
                       g_Bh + boff + k1, g_Bl + boff + k1, tid);
            CP_COMMIT();
            CP_WAIT(1);
        } else {
            CP_WAIT(0);
        }
        FENCE_ASYNC();
        __syncthreads();

        if (wid == 0 && elect_one()) {
            const uint32_t stg = sb + SM_DATA + buf * STAGE_BYTES;
            const uint64_t dAh = sdesc(stg);
            const uint64_t dAl = sdesc(stg + 16384);
            const uint64_t dBh = sdesc(stg + 32768);
            const uint64_t dBl = sdesc(stg + 49152);
            #pragma unroll
            for (int kk = 0; kk < 4; kk++) {       // 4 x K=16 per 64-chunk
                const uint64_t o = (uint64_t)(kk * 2);
                mma_f16_ss(tmem, dAh + o, dBh + o, IDESC, (c == 0 && kk == 0) ? 0u : 1u);
                mma_f16_ss(tmem, dAh + o, dBl + o, IDESC, 1u);
                mma_f16_ss(tmem, dAl + o, dBh + o, IDESC, 1u);
            }
            TC_COMMIT(sb + SM_MBAR + buf * 8);
        }
    }

    // epilogue: last chunk (7) committed to mbar[1]
    mbar_wait(sb + SM_MBAR + 8, wcnt1 & 1);
    TC_FENCE_AFTER();

    const int m = m0 + wid * 32 + lid;
    const bool valid = m < nt;
    float* crow = Ce + (size_t)m * N_ + n0;
    const float4 z = make_float4(0.f, 0.f, 0.f, 0.f);

    #pragma unroll
    for (int cb = 0; cb < BN; cb += 32) {
        uint32_t r[32];
        LDTM_X32(r, tmem + cb);
        TC_WAIT_LD();
        #pragma unroll
        for (int j = 0; j < 8; j++) {
            float4 v;
            if (valid) {
                v = make_float4(__uint_as_float(r[j * 4 + 0]), __uint_as_float(r[j * 4 + 1]),
                                __uint_as_float(r[j * 4 + 2]), __uint_as_float(r[j * 4 + 3]));
            } else {
                v = z;
            }
            *reinterpret_cast<float4*>(crow + cb + j * 4) = v;
        }
    }

    __syncthreads();
    if (tid == 0) { MBAR_INVAL(sb + SM_MBAR + 0); MBAR_INVAL(sb + SM_MBAR + 8); }
    __syncthreads();
    if (wid == 0) {
        TC_RELINQ();
        TC_DEALLOC(tmem, TMEM_COLS);
    }
#endif
}

// ======================= launch =======================
extern "C" void kernel_launch(void* const* d_in, const int* in_sizes, int n_in,
                              void* d_out, int out_size)
{
    const float* A   = (const float*)d_in[0];   // [E, M, K]
    const float* B   = (const float*)d_in[1];   // [E, N, K]
    const int*   ent = (const int*)d_in[2];     // [E]
    float*       C   = (float*)d_out;           // [E, M, N]

    convertA<<<2048, 256>>>(A, ent);
    convertB<<<2048, 256>>>(B);

    cudaFuncSetAttribute(grouped_gemm_tc,
                         cudaFuncAttributeMaxDynamicSharedMemorySize, SMEM_TOTAL);
    dim3 grid(N_ / BN, M_ / BM, E_);   // (4, 8, 32)
    grouped_gemm_tc<<<grid, NTHR, SMEM_TOTAL>>>(ent, C);
}